// round 2
// baseline (speedup 1.0000x reference)
#include <cuda_runtime.h>
#include <cuda_bf16.h>

// ---------------------------------------------------------------------------
// HexPlane feature sampling.
//   Inputs (metadata/dict order): xyz (N,3) f32, t (N,1) f32, bounds (1,2,3),
//     then 8 tables INTERLEAVED sp0,tp0,sp1,tp1,... — we dispatch by element
//     count so any ordering works:
//       sp_l: (3,8,r,r)   r=16<<l  -> sizes 6144, 24576, 98304, 393216
//       tp_l: (3,8,r,100)          -> sizes 38400, 76800, 153600, 307200
//   Output: (N, 192) f32; per point: [6 planes][4 levels][8 channels].
//
// Strategy:
//   1) transpose tables (3,C,H,W) -> (3,H,W,C) into __device__ scratch so one
//      texel's 8 channels are a contiguous 32B sector (2x float4 loads).
//   2) main kernel: 6 threads / point (one per plane), unrolled over 4 levels,
//      each thread writes 32 contiguous floats -> fully coalesced stores.
// ---------------------------------------------------------------------------

#define TAB_TOTAL 1098240
static __device__ float g_tables[TAB_TOTAL];

// Offsets (floats) of each level group inside g_tables:
// sp levels: 0, 6144, 30720, 129024
// tp levels: 522240, 560640, 637440, 791040

__global__ void transpose_tab(const float* __restrict__ src, int dstoff, int HW) {
    // src layout: (3, 8, HW); dst layout: (3, HW, 8) at g_tables + dstoff
    int i = blockIdx.x * blockDim.x + threadIdx.x;
    int total = 24 * HW;
    if (i >= total) return;
    int c   = i & 7;
    int r   = i >> 3;
    int pix = r % HW;
    int pl  = r / HW;
    g_tables[dstoff + i] = src[(pl * 8 + c) * HW + pix];
}

__device__ __forceinline__ float4 lerp4(float4 a, float4 b, float w) {
    float4 r;
    r.x = fmaf(w, b.x - a.x, a.x);
    r.y = fmaf(w, b.y - a.y, a.y);
    r.z = fmaf(w, b.z - a.z, a.z);
    r.w = fmaf(w, b.w - a.w, a.w);
    return r;
}

__global__ __launch_bounds__(256) void hex_main(
    const float* __restrict__ xyz,
    const float* __restrict__ tarr,
    const float* __restrict__ bounds,
    float* __restrict__ out,
    int N)
{
    int g = blockIdx.x * blockDim.x + threadIdx.x;
    if (g >= N * 6) return;
    int p     = g / 6;
    int plane = g - p * 6;

    // bounds: [lo0,lo1,lo2, hi0,hi1,hi2]
    float b0 = __ldg(bounds + 0), b1 = __ldg(bounds + 1), b2 = __ldg(bounds + 2);
    float b3 = __ldg(bounds + 3), b4 = __ldg(bounds + 4), b5 = __ldg(bounds + 5);

    float xn = __fdividef(__ldg(xyz + 3 * p + 0) - b0, b3 - b0);
    float yn = __fdividef(__ldg(xyz + 3 * p + 1) - b1, b4 - b1);
    float zn = __fdividef(__ldg(xyz + 3 * p + 2) - b2, b5 - b2);
    float tn = __ldg(tarr + p);

    bool sp = plane < 3;
    // gu per plane: {x, x, y, t, t, t}
    float gu = sp ? (plane == 2 ? yn : xn) : tn;
    // gv per plane: {y, z, z, x, y, z}
    float gv = (plane == 0 || plane == 4) ? yn : ((plane == 3) ? xn : zn);

    const int SPOFF[4] = {0, 6144, 30720, 129024};
    const int TPOFF[4] = {522240, 560640, 637440, 791040};

    float* o = out + (long)p * 192 + plane * 32;

    #pragma unroll
    for (int l = 0; l < 4; l++) {
        const int R = 16 << l;
        const int W = sp ? R : 100;
        const int H = R;

        float fW = (float)W;
        float fH = (float)H;

        // align_corners=false (spatial): ix = u*W - 0.5 ; true (temporal): ix = u*(W-1)
        float ix = sp ? fmaf(gu, fW, -0.5f) : gu * (fW - 1.0f);
        float iy = sp ? fmaf(gv, fH, -0.5f) : gv * (fH - 1.0f);
        ix = fminf(fmaxf(ix, 0.0f), fW - 1.0f);
        iy = fminf(fmaxf(iy, 0.0f), fH - 1.0f);

        float x0f = floorf(ix);
        float y0f = floorf(iy);
        float wx = ix - x0f;
        float wy = iy - y0f;
        int x0 = (int)x0f;
        int y0 = (int)y0f;
        int x1 = min(x0 + 1, W - 1);
        int y1 = min(y0 + 1, H - 1);

        const float* base = g_tables +
            (sp ? (SPOFF[l] + plane * 8 * R * R)
                : (TPOFF[l] + (plane - 3) * 8 * R * 100));
        const float4* b4p = (const float4*)base;

        int row0 = y0 * W;
        int row1 = y1 * W;

        // texel = 8 floats = 2 float4
        float4 v00a = __ldg(b4p + (row0 + x0) * 2 + 0);
        float4 v00b = __ldg(b4p + (row0 + x0) * 2 + 1);
        float4 v01a = __ldg(b4p + (row0 + x1) * 2 + 0);
        float4 v01b = __ldg(b4p + (row0 + x1) * 2 + 1);
        float4 v10a = __ldg(b4p + (row1 + x0) * 2 + 0);
        float4 v10b = __ldg(b4p + (row1 + x0) * 2 + 1);
        float4 v11a = __ldg(b4p + (row1 + x1) * 2 + 0);
        float4 v11b = __ldg(b4p + (row1 + x1) * 2 + 1);

        float4 topa = lerp4(v00a, v01a, wx);
        float4 topb = lerp4(v00b, v01b, wx);
        float4 bota = lerp4(v10a, v11a, wx);
        float4 botb = lerp4(v10b, v11b, wx);

        float4 ra = lerp4(topa, bota, wy);
        float4 rb = lerp4(topb, botb, wy);

        float4* o4 = (float4*)(o + l * 8);
        o4[0] = ra;
        o4[1] = rb;
    }
}

extern "C" void kernel_launch(void* const* d_in, const int* in_sizes, int n_in,
                              void* d_out, int out_size) {
    const float* xyz    = (const float*)d_in[0];
    const float* tarr   = (const float*)d_in[1];
    const float* bounds = (const float*)d_in[2];

    int N = in_sizes[0] / 3;

    // Identify table inputs BY SIZE (robust to metadata ordering; the dataset
    // dict interleaves sp_i and tp_i).
    // sp_l elems: 24*r*r  -> 6144, 24576, 98304, 393216
    // tp_l elems: 24*r*100-> 38400, 76800, 153600, 307200
    const float* sp[4] = {0, 0, 0, 0};
    const float* tp[4] = {0, 0, 0, 0};
    for (int j = 3; j < n_in; j++) {
        const float* ptr = (const float*)d_in[j];
        switch (in_sizes[j]) {
            case 6144:   sp[0] = ptr; break;
            case 24576:  sp[1] = ptr; break;
            case 98304:  sp[2] = ptr; break;
            case 393216: sp[3] = ptr; break;
            case 38400:  tp[0] = ptr; break;
            case 76800:  tp[1] = ptr; break;
            case 153600: tp[2] = ptr; break;
            case 307200: tp[3] = ptr; break;
            default: break;
        }
    }

    // {dst offset (floats), HW} for sp0..3 then tp0..3
    static const int cfg[8][2] = {
        {0,      16 * 16},   // sp0
        {6144,   32 * 32},   // sp1
        {30720,  64 * 64},   // sp2
        {129024, 128 * 128}, // sp3
        {522240, 16 * 100},  // tp0
        {560640, 32 * 100},  // tp1
        {637440, 64 * 100},  // tp2
        {791040, 128 * 100}, // tp3
    };
    for (int i = 0; i < 8; i++) {
        const float* src = (i < 4) ? sp[i] : tp[i - 4];
        int HW = cfg[i][1];
        int total = 24 * HW;
        transpose_tab<<<(total + 255) / 256, 256>>>(src, cfg[i][0], HW);
    }

    float* out = (float*)d_out;
    long threads = (long)N * 6;
    int blocks = (int)((threads + 255) / 256);
    hex_main<<<blocks, 256>>>(xyz, tarr, bounds, out, N);
}

// round 4
// speedup vs baseline: 1.5484x; 1.5484x over previous
#include <cuda_runtime.h>
#include <cuda_fp16.h>

// ---------------------------------------------------------------------------
// HexPlane feature sampling.
//   Tables are repacked (one fused kernel) from (3,C,H,W) fp32 into
//   channel-interleaved fp16: (3,H,W,C) — one texel = 16B = one float4 load.
//   Main kernel: 6 threads/point (one per plane), unrolled over 4 levels,
//   4 gather loads per level, fp32 interpolation, streaming 16B stores.
// ---------------------------------------------------------------------------

#define TAB_TOTAL 1098240
static __device__ __half g_tab[TAB_TOTAL];

// segment element counts / offsets (elements):
// sp0..3: 6144, 24576, 98304, 393216  @ 0, 6144, 30720, 129024
// tp0..3: 38400, 76800, 153600, 307200 @ 522240, 560640, 637440, 791040

struct TabSrc { const float* p[8]; };

__constant__ int c_segoff[9] = {0, 6144, 30720, 129024, 522240,
                                560640, 637440, 791040, 1098240};
__constant__ int c_seghw[8]  = {256, 1024, 4096, 16384,
                                1600, 3200, 6400, 12800};

__global__ void transpose_all(TabSrc s) {
    int i = blockIdx.x * blockDim.x + threadIdx.x;
    if (i >= TAB_TOTAL) return;
    int seg = 0;
    #pragma unroll
    for (int k = 1; k < 8; k++) seg += (i >= c_segoff[k]);
    int loc = i - c_segoff[seg];
    int HW  = c_seghw[seg];
    // dst layout (3, HW, 8): loc = ((pl*HW)+pix)*8 + c
    int c   = loc & 7;
    int r   = loc >> 3;
    int pix = r % HW;
    int pl  = r / HW;
    float v = s.p[seg][(pl * 8 + c) * HW + pix];
    g_tab[i] = __float2half_rn(v);
}

__device__ __forceinline__ void load_texel(const float4* __restrict__ b, int i,
                                           float* v) {
    float4 raw = __ldg(b + i);
    const __half2* h = (const __half2*)&raw;
    #pragma unroll
    for (int k = 0; k < 4; k++) {
        float2 f = __half22float2(h[k]);
        v[2 * k]     = f.x;
        v[2 * k + 1] = f.y;
    }
}

__global__ __launch_bounds__(256) void hex_main(
    const float* __restrict__ xyz,
    const float* __restrict__ tarr,
    const float* __restrict__ bounds,
    float* __restrict__ out,
    int N)
{
    int g = blockIdx.x * blockDim.x + threadIdx.x;
    if (g >= N * 6) return;
    int p     = g / 6;
    int plane = g - p * 6;

    float b0 = __ldg(bounds + 0), b1 = __ldg(bounds + 1), b2 = __ldg(bounds + 2);
    float b3 = __ldg(bounds + 3), b4 = __ldg(bounds + 4), b5 = __ldg(bounds + 5);

    float xn = __fdividef(__ldg(xyz + 3 * p + 0) - b0, b3 - b0);
    float yn = __fdividef(__ldg(xyz + 3 * p + 1) - b1, b4 - b1);
    float zn = __fdividef(__ldg(xyz + 3 * p + 2) - b2, b5 - b2);
    float tn = __ldg(tarr + p);

    bool sp = plane < 3;
    // gu per plane: {x, x, y, t, t, t}
    float gu = sp ? (plane == 2 ? yn : xn) : tn;
    // gv per plane: {y, z, z, x, y, z}
    float gv = (plane == 0 || plane == 4) ? yn : ((plane == 3) ? xn : zn);

    const int SPOFF[4] = {0, 6144, 30720, 129024};
    const int TPOFF[4] = {522240, 560640, 637440, 791040};

    float* o = out + (long)p * 192 + plane * 32;

    #pragma unroll
    for (int l = 0; l < 4; l++) {
        const int R = 16 << l;
        const int W = sp ? R : 100;
        const int H = R;

        float fW = (float)W;
        float fH = (float)H;

        // spatial: align_corners=false ; temporal: align_corners=true
        float ix = sp ? fmaf(gu, fW, -0.5f) : gu * (fW - 1.0f);
        float iy = sp ? fmaf(gv, fH, -0.5f) : gv * (fH - 1.0f);
        ix = fminf(fmaxf(ix, 0.0f), fW - 1.0f);
        iy = fminf(fmaxf(iy, 0.0f), fH - 1.0f);

        float x0f = floorf(ix);
        float y0f = floorf(iy);
        float wx = ix - x0f;
        float wy = iy - y0f;
        int x0 = (int)x0f;
        int y0 = (int)y0f;
        int x1 = min(x0 + 1, W - 1);
        int y1 = min(y0 + 1, H - 1);

        const __half* baseh = g_tab +
            (sp ? (SPOFF[l] + plane * 8 * R * R)
                : (TPOFF[l] + (plane - 3) * 8 * R * 100));
        const float4* b4p = (const float4*)baseh;   // one texel = 16B

        int row0 = y0 * W;
        int row1 = y1 * W;

        float v00[8], v01[8], v10[8], v11[8];
        load_texel(b4p, row0 + x0, v00);
        load_texel(b4p, row0 + x1, v01);
        load_texel(b4p, row1 + x0, v10);
        load_texel(b4p, row1 + x1, v11);

        float res[8];
        #pragma unroll
        for (int c = 0; c < 8; c++) {
            float top = fmaf(wx, v01[c] - v00[c], v00[c]);
            float bot = fmaf(wx, v11[c] - v10[c], v10[c]);
            res[c] = fmaf(wy, bot - top, top);
        }

        float4 ra = make_float4(res[0], res[1], res[2], res[3]);
        float4 rb = make_float4(res[4], res[5], res[6], res[7]);
        __stcs((float4*)(o + l * 8),     ra);
        __stcs((float4*)(o + l * 8) + 1, rb);
    }
}

extern "C" void kernel_launch(void* const* d_in, const int* in_sizes, int n_in,
                              void* d_out, int out_size) {
    const float* xyz    = (const float*)d_in[0];
    const float* tarr   = (const float*)d_in[1];
    const float* bounds = (const float*)d_in[2];

    int N = in_sizes[0] / 3;

    // Identify table inputs BY SIZE (dataset dict interleaves sp_i / tp_i).
    TabSrc src{};
    for (int j = 3; j < n_in; j++) {
        const float* ptr = (const float*)d_in[j];
        switch (in_sizes[j]) {
            case 6144:   src.p[0] = ptr; break;  // sp0
            case 24576:  src.p[1] = ptr; break;  // sp1
            case 98304:  src.p[2] = ptr; break;  // sp2
            case 393216: src.p[3] = ptr; break;  // sp3
            case 38400:  src.p[4] = ptr; break;  // tp0
            case 76800:  src.p[5] = ptr; break;  // tp1
            case 153600: src.p[6] = ptr; break;  // tp2
            case 307200: src.p[7] = ptr; break;  // tp3
            default: break;
        }
    }

    transpose_all<<<(TAB_TOTAL + 255) / 256, 256>>>(src);

    float* out = (float*)d_out;
    long threads = (long)N * 6;
    int blocks = (int)((threads + 255) / 256);
    hex_main<<<blocks, 256>>>(xyz, tarr, bounds, out, N);
}

// round 5
// speedup vs baseline: 1.6212x; 1.0471x over previous
#include <cuda_runtime.h>
#include <cuda_fp16.h>

// ---------------------------------------------------------------------------
// HexPlane feature sampling, R5.
//  - tables repacked fp16 channel-interleaved (3,H,W,C): texel = 16B.
//  - hex_main: persistent grid (1 block/SM, 512 thr), 6 threads/point.
//    * sp0, sp1, tp0 tables cached in shared memory (gathers via LDS).
//    * other segments gathered from global (L2-resident).
//    * outputs staged in smem (stride-513) -> fully coalesced float4 stores.
// ---------------------------------------------------------------------------

#define TAB_TOTAL 1098240
static __device__ __align__(16) __half g_tab[TAB_TOTAL];

// segment offsets (halves): sp0..3 @ 0,6144,30720,129024 ; tp0..3 @ 522240,...
struct TabSrc { const float* p[8]; };

__constant__ int c_segoff[9] = {0, 6144, 30720, 129024, 522240,
                                560640, 637440, 791040, 1098240};
__constant__ int c_seghw[8]  = {256, 1024, 4096, 16384,
                                1600, 3200, 6400, 12800};

__global__ void transpose_all(TabSrc s) {
    int i = blockIdx.x * blockDim.x + threadIdx.x;
    if (i >= TAB_TOTAL) return;
    int seg = 0;
    #pragma unroll
    for (int k = 1; k < 8; k++) seg += (i >= c_segoff[k]);
    int loc = i - c_segoff[seg];
    int HW  = c_seghw[seg];
    int c   = loc & 7;
    int r   = loc >> 3;
    int pix = r % HW;
    int pl  = r / HW;
    g_tab[i] = __float2half_rn(s.p[seg][(pl * 8 + c) * HW + pix]);
}

// smem layout: [tables 138240 B][stage 32*513 floats = 65664 B]
#define SMEM_TAB_BYTES 138240
#define STAGE_STRIDE   513
#define SMEM_TOTAL_BYTES (SMEM_TAB_BYTES + 32 * STAGE_STRIDE * 4)  // 203904

__device__ __forceinline__ void unpack_texel(float4 raw, float* v) {
    const __half2* h = (const __half2*)&raw;
    #pragma unroll
    for (int k = 0; k < 4; k++) {
        float2 f = __half22float2(h[k]);
        v[2 * k]     = f.x;
        v[2 * k + 1] = f.y;
    }
}

__global__ __launch_bounds__(512) void hex_main(
    const float* __restrict__ xyz,
    const float* __restrict__ tarr,
    const float* __restrict__ bounds,
    float* __restrict__ out,
    int N)
{
    extern __shared__ char smem[];
    __half* s_tab   = (__half*)smem;
    float*  s_stage = (float*)(smem + SMEM_TAB_BYTES);
    int tid = threadIdx.x;

    // Fill shared tables: sp0+sp1 (halves [0,30720)) and tp0 ([522240,560640)).
    {
        const uint4* src0 = (const uint4*)g_tab;              // 3840 x 16B
        uint4* dst0 = (uint4*)s_tab;
        for (int i = tid; i < 3840; i += 512) dst0[i] = src0[i];
        const uint4* src1 = (const uint4*)(g_tab + 522240);   // 4800 x 16B
        uint4* dst1 = (uint4*)(s_tab + 30720);
        for (int i = tid; i < 4800; i += 512) dst1[i] = src1[i];
    }
    __syncthreads();

    float b0 = __ldg(bounds + 0), b1 = __ldg(bounds + 1), b2 = __ldg(bounds + 2);
    float b3 = __ldg(bounds + 3), b4 = __ldg(bounds + 4), b5 = __ldg(bounds + 5);

    const int SPOFF[4] = {0, 6144, 30720, 129024};
    const int TPOFF[4] = {522240, 560640, 637440, 791040};

    int total  = N * 6;
    int stride = gridDim.x * 512;
    int iters  = (total + stride - 1) / stride;

    for (int it = 0; it < iters; ++it) {
        int gbase = blockIdx.x * 512 + it * stride;
        int g = gbase + tid;
        float r[32];
        bool active = (g < total);

        if (active) {
            int p     = g / 6;
            int plane = g - p * 6;

            float xn = __fdividef(__ldg(xyz + 3 * p + 0) - b0, b3 - b0);
            float yn = __fdividef(__ldg(xyz + 3 * p + 1) - b1, b4 - b1);
            float zn = __fdividef(__ldg(xyz + 3 * p + 2) - b2, b5 - b2);
            float tn = __ldg(tarr + p);

            bool sp = plane < 3;
            // gu per plane: {x, x, y, t, t, t}
            float gu = sp ? (plane == 2 ? yn : xn) : tn;
            // gv per plane: {y, z, z, x, y, z}
            float gv = (plane == 0 || plane == 4) ? yn
                     : ((plane == 3) ? xn : zn);

            #pragma unroll
            for (int l = 0; l < 4; l++) {
                const int R = 16 << l;
                const int W = sp ? R : 100;
                const int H = R;

                float fW = (float)W;
                float fH = (float)H;

                float ix = sp ? fmaf(gu, fW, -0.5f) : gu * (fW - 1.0f);
                float iy = sp ? fmaf(gv, fH, -0.5f) : gv * (fH - 1.0f);
                ix = fminf(fmaxf(ix, 0.0f), fW - 1.0f);
                iy = fminf(fmaxf(iy, 0.0f), fH - 1.0f);

                float x0f = floorf(ix);
                float y0f = floorf(iy);
                float wx = ix - x0f;
                float wy = iy - y0f;
                int x0 = (int)x0f;
                int y0 = (int)y0f;
                int x1 = min(x0 + 1, W - 1);
                int y1 = min(y0 + 1, H - 1);

                int row0 = y0 * W;
                int row1 = y1 * W;

                float v00[8], v01[8], v10[8], v11[8];

                bool use_s = (sp && l < 2) || (!sp && l == 0);
                if (use_s) {
                    // smem offsets (halves): sp0 plane*2048; sp1 6144+plane*8192;
                    // tp0 30720+(plane-3)*12800
                    int soff = sp ? (l == 0 ? plane * 2048 : 6144 + plane * 8192)
                                  : 30720 + (plane - 3) * 12800;
                    const float4* bp = (const float4*)(s_tab + soff);
                    unpack_texel(bp[row0 + x0], v00);
                    unpack_texel(bp[row0 + x1], v01);
                    unpack_texel(bp[row1 + x0], v10);
                    unpack_texel(bp[row1 + x1], v11);
                } else {
                    const __half* baseh = g_tab +
                        (sp ? (SPOFF[l] + plane * 8 * R * R)
                            : (TPOFF[l] + (plane - 3) * 8 * R * 100));
                    const float4* bp = (const float4*)baseh;
                    unpack_texel(__ldg(bp + row0 + x0), v00);
                    unpack_texel(__ldg(bp + row0 + x1), v01);
                    unpack_texel(__ldg(bp + row1 + x0), v10);
                    unpack_texel(__ldg(bp + row1 + x1), v11);
                }

                #pragma unroll
                for (int c = 0; c < 8; c++) {
                    float top = fmaf(wx, v01[c] - v00[c], v00[c]);
                    float bot = fmaf(wx, v11[c] - v10[c], v10[c]);
                    r[l * 8 + c] = fmaf(wy, bot - top, top);
                }
            }
        }

        __syncthreads();   // previous copy-out finished reading stage
        if (active) {
            #pragma unroll
            for (int c = 0; c < 32; c++)
                s_stage[c * STAGE_STRIDE + tid] = r[c];
        }
        __syncthreads();

        // Coalesced copy-out: region = floats [gbase*32, gbase*32 + 512*32)
        int f4base = gbase * 8;            // region base in float4 units
        int f4max  = total * 8;            // valid float4 count
        float4* out4 = (float4*)out;
        #pragma unroll
        for (int k = 0; k < 8; k++) {
            int f4loc = tid + 512 * k;
            int f4 = f4base + f4loc;
            if (f4 < f4max) {
                int lt = f4loc >> 3;               // source thread
                int c0 = (4 * tid) & 31;           // source channel base
                float4 v = make_float4(
                    s_stage[(c0 + 0) * STAGE_STRIDE + lt],
                    s_stage[(c0 + 1) * STAGE_STRIDE + lt],
                    s_stage[(c0 + 2) * STAGE_STRIDE + lt],
                    s_stage[(c0 + 3) * STAGE_STRIDE + lt]);
                __stcs(out4 + f4, v);
            }
        }
    }
}

extern "C" void kernel_launch(void* const* d_in, const int* in_sizes, int n_in,
                              void* d_out, int out_size) {
    const float* xyz    = (const float*)d_in[0];
    const float* tarr   = (const float*)d_in[1];
    const float* bounds = (const float*)d_in[2];

    int N = in_sizes[0] / 3;

    // Identify table inputs BY SIZE (dataset dict interleaves sp_i / tp_i).
    TabSrc src{};
    for (int j = 3; j < n_in; j++) {
        const float* ptr = (const float*)d_in[j];
        switch (in_sizes[j]) {
            case 6144:   src.p[0] = ptr; break;  // sp0
            case 24576:  src.p[1] = ptr; break;  // sp1
            case 98304:  src.p[2] = ptr; break;  // sp2
            case 393216: src.p[3] = ptr; break;  // sp3
            case 38400:  src.p[4] = ptr; break;  // tp0
            case 76800:  src.p[5] = ptr; break;  // tp1
            case 153600: src.p[6] = ptr; break;  // tp2
            case 307200: src.p[7] = ptr; break;  // tp3
            default: break;
        }
    }

    transpose_all<<<(TAB_TOTAL + 255) / 256, 256>>>(src);

    cudaFuncSetAttribute(hex_main,
                         cudaFuncAttributeMaxDynamicSharedMemorySize,
                         SMEM_TOTAL_BYTES);

    float* out = (float*)d_out;
    hex_main<<<148, 512, SMEM_TOTAL_BYTES>>>(xyz, tarr, bounds, out, N);
}

// round 7
// speedup vs baseline: 1.7349x; 1.0701x over previous
#include <cuda_runtime.h>
#include <cuda_fp16.h>

// ---------------------------------------------------------------------------
// HexPlane feature sampling, R7 (resubmit of R6 after infra flake).
//  - tables repacked fp16 channel-interleaved (3,H,W,C): texel = 16B.
//  - hex_main: 384-thr blocks (12 warps), warp w -> plane w/2 (warp-uniform
//    branches), 64 points per block-tile, persistent grid 296 (2 CTAs/SM).
//  - sp0+sp1 in shared memory (60 KB); sp2,sp3,tp0..3 via L2.
//  - output staged in smem float4[64][49] (conflict-free both phases) ->
//    fully coalesced float4 streaming stores.
// ---------------------------------------------------------------------------

#define TAB_TOTAL 1098240
static __device__ __align__(16) __half g_tab[TAB_TOTAL];

struct TabSrc { const float* p[8]; };

__constant__ int c_segoff[9] = {0, 6144, 30720, 129024, 522240,
                                560640, 637440, 791040, 1098240};
__constant__ int c_seghw[8]  = {256, 1024, 4096, 16384,
                                1600, 3200, 6400, 12800};

__global__ void transpose_all(TabSrc s) {
    int i = blockIdx.x * blockDim.x + threadIdx.x;
    if (i >= TAB_TOTAL) return;
    int seg = 0;
    #pragma unroll
    for (int k = 1; k < 8; k++) seg += (i >= c_segoff[k]);
    int loc = i - c_segoff[seg];
    int HW  = c_seghw[seg];
    int c   = loc & 7;
    int r   = loc >> 3;
    int pix = r % HW;
    int pl  = r / HW;
    g_tab[i] = __float2half_rn(s.p[seg][(pl * 8 + c) * HW + pix]);
}

// smem: [sp0+sp1 tables: 61440 B][stage: 64*49 float4 = 50176 B] = 111616 B
#define SMEM_TAB_BYTES 61440
#define STAGE_STRIDE_F4 49
#define SMEM_TOTAL_BYTES (SMEM_TAB_BYTES + 64 * STAGE_STRIDE_F4 * 16)

__device__ __forceinline__ void unpack_texel(float4 raw, float* v) {
    const __half2* h = (const __half2*)&raw;
    #pragma unroll
    for (int k = 0; k < 4; k++) {
        float2 f = __half22float2(h[k]);
        v[2 * k]     = f.x;
        v[2 * k + 1] = f.y;
    }
}

__global__ __launch_bounds__(384, 2) void hex_main(
    const float* __restrict__ xyz,
    const float* __restrict__ tarr,
    const float* __restrict__ bounds,
    float* __restrict__ out,
    int N)
{
    extern __shared__ char smem[];
    __half* s_tab    = (__half*)smem;
    float4* s_stage4 = (float4*)(smem + SMEM_TAB_BYTES);
    int tid = threadIdx.x;

    // Fill shared tables: sp0+sp1 = halves [0, 30720) of g_tab.
    {
        const uint4* src = (const uint4*)g_tab;   // 3840 x 16B
        uint4* dst = (uint4*)s_tab;
        for (int i = tid; i < 3840; i += 384) dst[i] = src[i];
    }
    __syncthreads();

    float b0 = __ldg(bounds + 0), b1 = __ldg(bounds + 1), b2 = __ldg(bounds + 2);
    float b3 = __ldg(bounds + 3), b4 = __ldg(bounds + 4), b5 = __ldg(bounds + 5);

    const int SPOFF[4] = {0, 6144, 30720, 129024};
    const int TPOFF[4] = {522240, 560640, 637440, 791040};

    int w     = tid >> 5;
    int lane  = tid & 31;
    int plane = w >> 1;                  // warp-uniform
    int q     = ((w & 1) << 5) | lane;   // point slot in tile [0,64)
    bool sp   = plane < 3;               // warp-uniform

    int ntiles = (N + 63) >> 6;
    long f4max = (long)N * 48;

    for (int tile = blockIdx.x; tile < ntiles; tile += gridDim.x) {
        int p = tile * 64 + q;
        bool active = (p < N);
        float4 r4[8];

        if (active) {
            float xn = __fdividef(__ldg(xyz + 3 * p + 0) - b0, b3 - b0);
            float yn = __fdividef(__ldg(xyz + 3 * p + 1) - b1, b4 - b1);
            float zn = __fdividef(__ldg(xyz + 3 * p + 2) - b2, b5 - b2);
            float tn = __ldg(tarr + p);

            // gu per plane: {x, x, y, t, t, t}
            float gu = sp ? (plane == 2 ? yn : xn) : tn;
            // gv per plane: {y, z, z, x, y, z}
            float gv = (plane == 0 || plane == 4) ? yn
                     : ((plane == 3) ? xn : zn);

            #pragma unroll
            for (int l = 0; l < 4; l++) {
                const int R = 16 << l;
                const int W = sp ? R : 100;
                const int H = R;

                float fW = (float)W;
                float fH = (float)H;

                // spatial: align_corners=false ; temporal: align_corners=true
                float ix = sp ? fmaf(gu, fW, -0.5f) : gu * (fW - 1.0f);
                float iy = sp ? fmaf(gv, fH, -0.5f) : gv * (fH - 1.0f);
                ix = fminf(fmaxf(ix, 0.0f), fW - 1.0f);
                iy = fminf(fmaxf(iy, 0.0f), fH - 1.0f);

                float x0f = floorf(ix);
                float y0f = floorf(iy);
                float wx = ix - x0f;
                float wy = iy - y0f;
                int x0 = (int)x0f;
                int y0 = (int)y0f;
                int x1 = min(x0 + 1, W - 1);
                int y1 = min(y0 + 1, H - 1);

                int row0 = y0 * W;
                int row1 = y1 * W;

                float v00[8], v01[8], v10[8], v11[8];

                bool use_s = sp && (l < 2);   // warp-uniform
                if (use_s) {
                    int soff = (l == 0) ? plane * 2048 : 6144 + plane * 8192;
                    const float4* bp = (const float4*)(s_tab + soff);
                    unpack_texel(bp[row0 + x0], v00);
                    unpack_texel(bp[row0 + x1], v01);
                    unpack_texel(bp[row1 + x0], v10);
                    unpack_texel(bp[row1 + x1], v11);
                } else {
                    const __half* baseh = g_tab +
                        (sp ? (SPOFF[l] + plane * 8 * R * R)
                            : (TPOFF[l] + (plane - 3) * 8 * R * 100));
                    const float4* bp = (const float4*)baseh;
                    unpack_texel(__ldg(bp + row0 + x0), v00);
                    unpack_texel(__ldg(bp + row0 + x1), v01);
                    unpack_texel(__ldg(bp + row1 + x0), v10);
                    unpack_texel(__ldg(bp + row1 + x1), v11);
                }

                float res[8];
                #pragma unroll
                for (int c = 0; c < 8; c++) {
                    float top = fmaf(wx, v01[c] - v00[c], v00[c]);
                    float bot = fmaf(wx, v11[c] - v10[c], v10[c]);
                    res[c] = fmaf(wy, bot - top, top);
                }
                r4[2 * l]     = make_float4(res[0], res[1], res[2], res[3]);
                r4[2 * l + 1] = make_float4(res[4], res[5], res[6], res[7]);
            }
        }

        __syncthreads();   // previous copy-out done reading stage
        {
            // stage write: point q, f4 columns [plane*8, plane*8+8)
            float4* sw = s_stage4 + q * STAGE_STRIDE_F4 + plane * 8;
            #pragma unroll
            for (int j = 0; j < 8; j++) sw[j] = r4[j];
        }
        __syncthreads();

        // Coalesced copy-out: 3072 float4 = 64 points x 48 f4
        long f4base = (long)tile * 3072;
        float4* out4 = (float4*)out;
        #pragma unroll
        for (int k = 0; k < 8; k++) {
            int f = tid + 384 * k;
            long f4 = f4base + f;
            if (f4 < f4max) {
                int q2 = f / 48;
                int c4 = f - q2 * 48;
                __stcs(out4 + f4, s_stage4[q2 * STAGE_STRIDE_F4 + c4]);
            }
        }
    }
}

extern "C" void kernel_launch(void* const* d_in, const int* in_sizes, int n_in,
                              void* d_out, int out_size) {
    const float* xyz    = (const float*)d_in[0];
    const float* tarr   = (const float*)d_in[1];
    const float* bounds = (const float*)d_in[2];

    int N = in_sizes[0] / 3;

    // Identify table inputs BY SIZE (dataset dict interleaves sp_i / tp_i).
    TabSrc src{};
    for (int j = 3; j < n_in; j++) {
        const float* ptr = (const float*)d_in[j];
        switch (in_sizes[j]) {
            case 6144:   src.p[0] = ptr; break;  // sp0
            case 24576:  src.p[1] = ptr; break;  // sp1
            case 98304:  src.p[2] = ptr; break;  // sp2
            case 393216: src.p[3] = ptr; break;  // sp3
            case 38400:  src.p[4] = ptr; break;  // tp0
            case 76800:  src.p[5] = ptr; break;  // tp1
            case 153600: src.p[6] = ptr; break;  // tp2
            case 307200: src.p[7] = ptr; break;  // tp3
            default: break;
        }
    }

    transpose_all<<<(TAB_TOTAL + 255) / 256, 256>>>(src);

    cudaFuncSetAttribute(hex_main,
                         cudaFuncAttributeMaxDynamicSharedMemorySize,
                         SMEM_TOTAL_BYTES);

    float* out = (float*)d_out;
    hex_main<<<296, 384, SMEM_TOTAL_BYTES>>>(xyz, tarr, bounds, out, N);
}

// round 8
// speedup vs baseline: 1.8980x; 1.0940x over previous
#include <cuda_runtime.h>
#include <cuda_fp16.h>

// ---------------------------------------------------------------------------
// HexPlane feature sampling, R8: per-plane Morton-sorted gathers.
//  1) transpose_all: tables -> fp16 channel-interleaved (3,H,W,C), texel=16B.
//  2) counting sort per plane (6x): 16-bit Morton key of that plane's (u,v).
//     zero_hist -> hist -> scan (6 blocks) -> scatter (writes float4{u,v,p}).
//  3) hex_main: block=192 (6 warps), warp w = plane w, 32 sorted points/warp.
//     All lanes of a warp hit nearly the same texels -> ~1 wf per gather LDG.
//     Output staged per-warp in smem -> coalesced 128B-per-point stores.
// ---------------------------------------------------------------------------

#define TAB_TOTAL 1098240
#define NMAX 1048576
#define NBUCK 65536

static __device__ __align__(16) __half g_tab[TAB_TOTAL];
static __device__ int    g_hist[6 * NBUCK];
static __device__ __align__(16) float4 g_pt[6 * NMAX];   // (u, v, bits(p), -)

struct TabSrc { const float* p[8]; };

__constant__ int c_segoff[9] = {0, 6144, 30720, 129024, 522240,
                                560640, 637440, 791040, 1098240};
__constant__ int c_seghw[8]  = {256, 1024, 4096, 16384,
                                1600, 3200, 6400, 12800};

__global__ void transpose_all(TabSrc s) {
    int i = blockIdx.x * blockDim.x + threadIdx.x;
    if (i >= TAB_TOTAL) return;
    int seg = 0;
    #pragma unroll
    for (int k = 1; k < 8; k++) seg += (i >= c_segoff[k]);
    int loc = i - c_segoff[seg];
    int HW  = c_seghw[seg];
    int c   = loc & 7;
    int r   = loc >> 3;
    int pix = r % HW;
    int pl  = r / HW;
    g_tab[i] = __float2half_rn(s.p[seg][(pl * 8 + c) * HW + pix]);
}

// ---- sorting machinery -----------------------------------------------------

__device__ __forceinline__ unsigned part1by1(unsigned x) {
    x &= 0xFF;
    x = (x | (x << 4)) & 0x0F0F;
    x = (x | (x << 2)) & 0x3333;
    x = (x | (x << 1)) & 0x5555;
    return x;
}

__device__ __forceinline__ void plane_uv(int pl, float x, float y, float z,
                                         float t, float& u, float& v) {
    // gu per plane: {x, x, y, t, t, t}; gv per plane: {y, z, z, x, y, z}
    u = pl < 3 ? (pl == 2 ? y : x) : t;
    v = (pl == 0 || pl == 4) ? y : (pl == 3 ? x : z);
}

__device__ __forceinline__ int key16(float u, float v) {
    int ku = min(255, (int)(__saturatef(u) * 256.0f));
    int kv = min(255, (int)(__saturatef(v) * 256.0f));
    return (int)(part1by1(ku) | (part1by1(kv) << 1));
}

__global__ void zero_hist() {
    int i = blockIdx.x * blockDim.x + threadIdx.x;
    if (i < 6 * NBUCK) g_hist[i] = 0;
}

__device__ __forceinline__ void norm_pt(const float* xyz, const float* tarr,
                                        const float* bounds, int p,
                                        float& xn, float& yn, float& zn,
                                        float& tn) {
    float b0 = __ldg(bounds + 0), b1 = __ldg(bounds + 1), b2 = __ldg(bounds + 2);
    float b3 = __ldg(bounds + 3), b4 = __ldg(bounds + 4), b5 = __ldg(bounds + 5);
    xn = __fdividef(__ldg(xyz + 3 * p + 0) - b0, b3 - b0);
    yn = __fdividef(__ldg(xyz + 3 * p + 1) - b1, b4 - b1);
    zn = __fdividef(__ldg(xyz + 3 * p + 2) - b2, b5 - b2);
    tn = __ldg(tarr + p);
}

__global__ void hist_k(const float* __restrict__ xyz,
                       const float* __restrict__ tarr,
                       const float* __restrict__ bounds, int N) {
    int p = blockIdx.x * blockDim.x + threadIdx.x;
    if (p >= N) return;
    float xn, yn, zn, tn;
    norm_pt(xyz, tarr, bounds, p, xn, yn, zn, tn);
    #pragma unroll
    for (int pl = 0; pl < 6; pl++) {
        float u, v;
        plane_uv(pl, xn, yn, zn, tn, u, v);
        atomicAdd(&g_hist[pl * NBUCK + key16(u, v)], 1);
    }
}

__global__ void scan_k() {
    // one block per plane; 1024 threads x 64 buckets each; in-place exclusive.
    int* h = g_hist + blockIdx.x * NBUCK;
    int tid = threadIdx.x;
    int base = tid * 64;
    int sum = 0;
    for (int i = 0; i < 64; i++) sum += h[base + i];
    __shared__ int sm[1024];
    sm[tid] = sum;
    __syncthreads();
    for (int off = 1; off < 1024; off <<= 1) {
        int v = (tid >= off) ? sm[tid - off] : 0;
        __syncthreads();
        sm[tid] += v;
        __syncthreads();
    }
    int c = sm[tid] - sum;   // exclusive prefix of this chunk
    for (int i = 0; i < 64; i++) {
        int v = h[base + i];
        h[base + i] = c;
        c += v;
    }
}

__global__ void scatter_k(const float* __restrict__ xyz,
                          const float* __restrict__ tarr,
                          const float* __restrict__ bounds, int N) {
    int p = blockIdx.x * blockDim.x + threadIdx.x;
    if (p >= N) return;
    float xn, yn, zn, tn;
    norm_pt(xyz, tarr, bounds, p, xn, yn, zn, tn);
    #pragma unroll
    for (int pl = 0; pl < 6; pl++) {
        float u, v;
        plane_uv(pl, xn, yn, zn, tn, u, v);
        int pos = atomicAdd(&g_hist[pl * NBUCK + key16(u, v)], 1);
        g_pt[pl * NMAX + pos] = make_float4(u, v, __int_as_float(p), 0.0f);
    }
}

// ---- main sampling kernel ---------------------------------------------------

__device__ __forceinline__ void unpack_texel(float4 raw, float* v) {
    const __half2* h = (const __half2*)&raw;
    #pragma unroll
    for (int k = 0; k < 4; k++) {
        float2 f = __half22float2(h[k]);
        v[2 * k]     = f.x;
        v[2 * k + 1] = f.y;
    }
}

__global__ __launch_bounds__(192) void hex_main(float* __restrict__ out, int N) {
    __shared__ float4 stage[6][32][9];   // stride 9 f4: conflict-free
    int w    = threadIdx.x >> 5;         // plane (warp-uniform)
    int lane = threadIdx.x & 31;
    long tilebase = (long)blockIdx.x * 32;
    int  idx = (int)tilebase + lane;
    bool act = idx < N;

    float u = 0.0f, v = 0.0f;
    int p = 0;
    if (act) {
        float4 pr = __ldg(&g_pt[w * NMAX + idx]);
        u = pr.x; v = pr.y; p = __float_as_int(pr.z);
    }
    bool sp = w < 3;

    const int SPOFF[4] = {0, 6144, 30720, 129024};
    const int TPOFF[4] = {522240, 560640, 637440, 791040};

    float4 r4[8];
    #pragma unroll
    for (int l = 0; l < 4; l++) {
        const int R = 16 << l;
        const int W = sp ? R : 100;
        const int H = R;
        float fW = (float)W, fH = (float)H;

        // spatial: align_corners=false ; temporal: align_corners=true
        float ix = sp ? fmaf(u, fW, -0.5f) : u * (fW - 1.0f);
        float iy = sp ? fmaf(v, fH, -0.5f) : v * (fH - 1.0f);
        ix = fminf(fmaxf(ix, 0.0f), fW - 1.0f);
        iy = fminf(fmaxf(iy, 0.0f), fH - 1.0f);

        float x0f = floorf(ix);
        float y0f = floorf(iy);
        float wx = ix - x0f;
        float wy = iy - y0f;
        int x0 = (int)x0f;
        int y0 = (int)y0f;
        int x1 = min(x0 + 1, W - 1);
        int y1 = min(y0 + 1, H - 1);

        const __half* baseh = g_tab +
            (sp ? (SPOFF[l] + w * 8 * R * R)
                : (TPOFF[l] + (w - 3) * 8 * R * 100));
        const float4* bp = (const float4*)baseh;

        int row0 = y0 * W;
        int row1 = y1 * W;

        float v00[8], v01[8], v10[8], v11[8];
        unpack_texel(__ldg(bp + row0 + x0), v00);
        unpack_texel(__ldg(bp + row0 + x1), v01);
        unpack_texel(__ldg(bp + row1 + x0), v10);
        unpack_texel(__ldg(bp + row1 + x1), v11);

        float res[8];
        #pragma unroll
        for (int c = 0; c < 8; c++) {
            float top = fmaf(wx, v01[c] - v00[c], v00[c]);
            float bot = fmaf(wx, v11[c] - v10[c], v10[c]);
            res[c] = fmaf(wy, bot - top, top);
        }
        r4[2 * l]     = make_float4(res[0], res[1], res[2], res[3]);
        r4[2 * l + 1] = make_float4(res[4], res[5], res[6], res[7]);
    }

    // warp-local stage (no block barrier needed)
    #pragma unroll
    for (int j = 0; j < 8; j++) stage[w][lane][j] = r4[j];
    __syncwarp();

    // cooperative write-out: round r covers points r*4..r*4+3, 8 f4 each.
    float4* out4 = (float4*)out;
    #pragma unroll
    for (int r = 0; r < 8; r++) {
        int pt = r * 4 + (lane >> 3);
        int c4 = lane & 7;
        int pp = __shfl_sync(0xffffffffu, p, pt);
        float4 val = stage[w][pt][c4];
        if (tilebase + pt < N)
            __stcs(out4 + (long)pp * 48 + w * 8 + c4, val);
    }
}

// ---- host glue ---------------------------------------------------------------

extern "C" void kernel_launch(void* const* d_in, const int* in_sizes, int n_in,
                              void* d_out, int out_size) {
    const float* xyz    = (const float*)d_in[0];
    const float* tarr   = (const float*)d_in[1];
    const float* bounds = (const float*)d_in[2];

    int N = in_sizes[0] / 3;

    // Identify table inputs BY SIZE (dataset dict interleaves sp_i / tp_i).
    TabSrc src{};
    for (int j = 3; j < n_in; j++) {
        const float* ptr = (const float*)d_in[j];
        switch (in_sizes[j]) {
            case 6144:   src.p[0] = ptr; break;  // sp0
            case 24576:  src.p[1] = ptr; break;  // sp1
            case 98304:  src.p[2] = ptr; break;  // sp2
            case 393216: src.p[3] = ptr; break;  // sp3
            case 38400:  src.p[4] = ptr; break;  // tp0
            case 76800:  src.p[5] = ptr; break;  // tp1
            case 153600: src.p[6] = ptr; break;  // tp2
            case 307200: src.p[7] = ptr; break;  // tp3
            default: break;
        }
    }

    transpose_all<<<(TAB_TOTAL + 255) / 256, 256>>>(src);
    zero_hist<<<(6 * NBUCK + 1023) / 1024, 1024>>>();
    hist_k<<<(N + 255) / 256, 256>>>(xyz, tarr, bounds, N);
    scan_k<<<6, 1024>>>();
    scatter_k<<<(N + 255) / 256, 256>>>(xyz, tarr, bounds, N);

    hex_main<<<(N + 31) / 32, 192>>>((float*)d_out, N);
}

// round 10
// speedup vs baseline: 2.6127x; 1.3765x over previous
#include <cuda_runtime.h>
#include <cuda_fp16.h>

// ---------------------------------------------------------------------------
// HexPlane feature sampling, R10 (resubmit of R9 after periodic infra flake).
//  1) transpose_all: tables -> fp16 channel-interleaved (3,H,W,C), texel=16B.
//  2) counting sort per plane (6x): 14-bit Morton key (128x128 grid).
//     zero_hist -> hist -> scan_blocks/scan_tops/add_offs -> scatter.
//  3) hex_main: block=192 (6 warps), warp w = plane w, 32 sorted points/warp.
// ---------------------------------------------------------------------------

#define TAB_TOTAL 1098240
#define NMAX 1048576
#define NBUCK 16384          // 14-bit key: 128x128 Morton grid
#define NSCANBLK 192         // 6*NBUCK / 512

static __device__ __align__(16) __half g_tab[TAB_TOTAL];
static __device__ int    g_hist[6 * NBUCK];
static __device__ int    g_bsum[NSCANBLK];
static __device__ __align__(16) float4 g_pt[6 * NMAX];   // (u, v, bits(p), -)

struct TabSrc { const float* p[8]; };

__constant__ int c_segoff[9] = {0, 6144, 30720, 129024, 522240,
                                560640, 637440, 791040, 1098240};
__constant__ int c_seghw[8]  = {256, 1024, 4096, 16384,
                                1600, 3200, 6400, 12800};

__global__ void transpose_all(TabSrc s) {
    int i = blockIdx.x * blockDim.x + threadIdx.x;
    if (i >= TAB_TOTAL) return;
    int seg = 0;
    #pragma unroll
    for (int k = 1; k < 8; k++) seg += (i >= c_segoff[k]);
    int loc = i - c_segoff[seg];
    int HW  = c_seghw[seg];
    int c   = loc & 7;
    int r   = loc >> 3;
    int pix = r % HW;
    int pl  = r / HW;
    g_tab[i] = __float2half_rn(s.p[seg][(pl * 8 + c) * HW + pix]);
}

// ---- sorting machinery -----------------------------------------------------

__device__ __forceinline__ unsigned part1by1(unsigned x) {
    x &= 0x7F;
    x = (x | (x << 4)) & 0x0F0F;
    x = (x | (x << 2)) & 0x3333;
    x = (x | (x << 1)) & 0x5555;
    return x;
}

__device__ __forceinline__ void plane_uv(int pl, float x, float y, float z,
                                         float t, float& u, float& v) {
    // gu per plane: {x, x, y, t, t, t}; gv per plane: {y, z, z, x, y, z}
    u = pl < 3 ? (pl == 2 ? y : x) : t;
    v = (pl == 0 || pl == 4) ? y : (pl == 3 ? x : z);
}

__device__ __forceinline__ int key14(float u, float v) {
    int ku = min(127, (int)(__saturatef(u) * 128.0f));
    int kv = min(127, (int)(__saturatef(v) * 128.0f));
    return (int)(part1by1(ku) | (part1by1(kv) << 1));
}

__global__ void zero_hist() {
    int i = blockIdx.x * blockDim.x + threadIdx.x;
    if (i < 6 * NBUCK) g_hist[i] = 0;
}

__device__ __forceinline__ void norm_pt(const float* xyz, const float* tarr,
                                        const float* bounds, int p,
                                        float& xn, float& yn, float& zn,
                                        float& tn) {
    float b0 = __ldg(bounds + 0), b1 = __ldg(bounds + 1), b2 = __ldg(bounds + 2);
    float b3 = __ldg(bounds + 3), b4 = __ldg(bounds + 4), b5 = __ldg(bounds + 5);
    xn = __fdividef(__ldg(xyz + 3 * p + 0) - b0, b3 - b0);
    yn = __fdividef(__ldg(xyz + 3 * p + 1) - b1, b4 - b1);
    zn = __fdividef(__ldg(xyz + 3 * p + 2) - b2, b5 - b2);
    tn = __ldg(tarr + p);
}

__global__ void hist_k(const float* __restrict__ xyz,
                       const float* __restrict__ tarr,
                       const float* __restrict__ bounds, int N) {
    int p = blockIdx.x * blockDim.x + threadIdx.x;
    if (p >= N) return;
    float xn, yn, zn, tn;
    norm_pt(xyz, tarr, bounds, p, xn, yn, zn, tn);
    #pragma unroll
    for (int pl = 0; pl < 6; pl++) {
        float u, v;
        plane_uv(pl, xn, yn, zn, tn, u, v);
        atomicAdd(&g_hist[pl * NBUCK + key14(u, v)], 1);
    }
}

// Phase 1: block-local exclusive scan of 512 buckets; emit block total.
__global__ void scan_blocks() {
    __shared__ int sm[512];
    int gbase = blockIdx.x * 512;
    int tid = threadIdx.x;
    int v = g_hist[gbase + tid];
    sm[tid] = v;
    __syncthreads();
    #pragma unroll
    for (int off = 1; off < 512; off <<= 1) {
        int t = (tid >= off) ? sm[tid - off] : 0;
        __syncthreads();
        sm[tid] += t;
        __syncthreads();
    }
    g_hist[gbase + tid] = sm[tid] - v;   // exclusive
    if (tid == 511) g_bsum[blockIdx.x] = sm[511];
}

// Phase 2: per-plane exclusive scan of the 32 block sums (6 warps).
__global__ void scan_tops() {
    int w = threadIdx.x >> 5, lane = threadIdx.x & 31;
    if (w < 6) {
        int i = w * 32 + lane;
        int v = g_bsum[i];
        int s = v;
        #pragma unroll
        for (int off = 1; off < 32; off <<= 1) {
            int t = __shfl_up_sync(0xffffffffu, s, off);
            if (lane >= off) s += t;
        }
        g_bsum[i] = s - v;
    }
}

// Phase 3: add block offsets.
__global__ void add_offs() {
    int i = blockIdx.x * blockDim.x + threadIdx.x;
    if (i < 6 * NBUCK) g_hist[i] += g_bsum[i >> 9];
}

__global__ void scatter_k(const float* __restrict__ xyz,
                          const float* __restrict__ tarr,
                          const float* __restrict__ bounds, int N) {
    int p = blockIdx.x * blockDim.x + threadIdx.x;
    if (p >= N) return;
    float xn, yn, zn, tn;
    norm_pt(xyz, tarr, bounds, p, xn, yn, zn, tn);
    #pragma unroll
    for (int pl = 0; pl < 6; pl++) {
        float u, v;
        plane_uv(pl, xn, yn, zn, tn, u, v);
        int pos = atomicAdd(&g_hist[pl * NBUCK + key14(u, v)], 1);
        g_pt[pl * NMAX + pos] = make_float4(u, v, __int_as_float(p), 0.0f);
    }
}

// ---- main sampling kernel ---------------------------------------------------

__device__ __forceinline__ void unpack_texel(float4 raw, float* v) {
    const __half2* h = (const __half2*)&raw;
    #pragma unroll
    for (int k = 0; k < 4; k++) {
        float2 f = __half22float2(h[k]);
        v[2 * k]     = f.x;
        v[2 * k + 1] = f.y;
    }
}

__global__ __launch_bounds__(192) void hex_main(float* __restrict__ out, int N) {
    __shared__ float4 stage[6][32][9];   // stride 9 f4: conflict-free
    int w    = threadIdx.x >> 5;         // plane (warp-uniform)
    int lane = threadIdx.x & 31;
    long tilebase = (long)blockIdx.x * 32;
    int  idx = (int)tilebase + lane;
    bool act = idx < N;

    float u = 0.0f, v = 0.0f;
    int p = 0;
    if (act) {
        float4 pr = __ldg(&g_pt[w * NMAX + idx]);
        u = pr.x; v = pr.y; p = __float_as_int(pr.z);
    }
    bool sp = w < 3;

    const int SPOFF[4] = {0, 6144, 30720, 129024};
    const int TPOFF[4] = {522240, 560640, 637440, 791040};

    float4 r4[8];
    #pragma unroll
    for (int l = 0; l < 4; l++) {
        const int R = 16 << l;
        const int W = sp ? R : 100;
        const int H = R;
        float fW = (float)W, fH = (float)H;

        // spatial: align_corners=false ; temporal: align_corners=true
        float ix = sp ? fmaf(u, fW, -0.5f) : u * (fW - 1.0f);
        float iy = sp ? fmaf(v, fH, -0.5f) : v * (fH - 1.0f);
        ix = fminf(fmaxf(ix, 0.0f), fW - 1.0f);
        iy = fminf(fmaxf(iy, 0.0f), fH - 1.0f);

        float x0f = floorf(ix);
        float y0f = floorf(iy);
        float wx = ix - x0f;
        float wy = iy - y0f;
        int x0 = (int)x0f;
        int y0 = (int)y0f;
        int x1 = min(x0 + 1, W - 1);
        int y1 = min(y0 + 1, H - 1);

        const __half* baseh = g_tab +
            (sp ? (SPOFF[l] + w * 8 * R * R)
                : (TPOFF[l] + (w - 3) * 8 * R * 100));
        const float4* bp = (const float4*)baseh;

        int row0 = y0 * W;
        int row1 = y1 * W;

        float v00[8], v01[8], v10[8], v11[8];
        unpack_texel(__ldg(bp + row0 + x0), v00);
        unpack_texel(__ldg(bp + row0 + x1), v01);
        unpack_texel(__ldg(bp + row1 + x0), v10);
        unpack_texel(__ldg(bp + row1 + x1), v11);

        float res[8];
        #pragma unroll
        for (int c = 0; c < 8; c++) {
            float top = fmaf(wx, v01[c] - v00[c], v00[c]);
            float bot = fmaf(wx, v11[c] - v10[c], v10[c]);
            res[c] = fmaf(wy, bot - top, top);
        }
        r4[2 * l]     = make_float4(res[0], res[1], res[2], res[3]);
        r4[2 * l + 1] = make_float4(res[4], res[5], res[6], res[7]);
    }

    // warp-local stage (no block barrier needed)
    #pragma unroll
    for (int j = 0; j < 8; j++) stage[w][lane][j] = r4[j];
    __syncwarp();

    // cooperative write-out: round r covers points r*4..r*4+3, 8 f4 each.
    float4* out4 = (float4*)out;
    #pragma unroll
    for (int r = 0; r < 8; r++) {
        int pt = r * 4 + (lane >> 3);
        int c4 = lane & 7;
        int pp = __shfl_sync(0xffffffffu, p, pt);
        float4 val = stage[w][pt][c4];
        if (tilebase + pt < N)
            __stcs(out4 + (long)pp * 48 + w * 8 + c4, val);
    }
}

// ---- host glue ---------------------------------------------------------------

extern "C" void kernel_launch(void* const* d_in, const int* in_sizes, int n_in,
                              void* d_out, int out_size) {
    const float* xyz    = (const float*)d_in[0];
    const float* tarr   = (const float*)d_in[1];
    const float* bounds = (const float*)d_in[2];

    int N = in_sizes[0] / 3;

    // Identify table inputs BY SIZE (dataset dict interleaves sp_i / tp_i).
    TabSrc src{};
    for (int j = 3; j < n_in; j++) {
        const float* ptr = (const float*)d_in[j];
        switch (in_sizes[j]) {
            case 6144:   src.p[0] = ptr; break;  // sp0
            case 24576:  src.p[1] = ptr; break;  // sp1
            case 98304:  src.p[2] = ptr; break;  // sp2
            case 393216: src.p[3] = ptr; break;  // sp3
            case 38400:  src.p[4] = ptr; break;  // tp0
            case 76800:  src.p[5] = ptr; break;  // tp1
            case 153600: src.p[6] = ptr; break;  // tp2
            case 307200: src.p[7] = ptr; break;  // tp3
            default: break;
        }
    }

    transpose_all<<<(TAB_TOTAL + 255) / 256, 256>>>(src);
    zero_hist<<<(6 * NBUCK + 1023) / 1024, 1024>>>();
    hist_k<<<(N + 255) / 256, 256>>>(xyz, tarr, bounds, N);
    scan_blocks<<<NSCANBLK, 512>>>();
    scan_tops<<<1, 192>>>();
    add_offs<<<(6 * NBUCK + 1023) / 1024, 1024>>>();
    scatter_k<<<(N + 255) / 256, 256>>>(xyz, tarr, bounds, N);

    hex_main<<<(N + 31) / 32, 192>>>((float*)d_out, N);
}